// round 15
// baseline (speedup 1.0000x reference)
#include <cuda_runtime.h>
#include <cuda_fp16.h>
#include <math_constants.h>
#include <stdint.h>

// Problem constants (shapes fixed by the reference).
#define MAX_N 100032
#define MAX_E 1600000
#define D_IN  128
#define D_OUT 64

#define ROW_W 68     // half2-words per smem row (64 data + 4 pad); 272 B, 16B-aligned
#define OS_PAD 68    // epilogue float pitch (overlays Ash exactly)

// ---------------- Scratch (static __device__ globals; no runtime allocs) ---
// g_deg is zero at module load; k_scatter re-zeroes it for the NEXT invocation
// (graph replays run the identical sequence, so the invariant holds).
__device__ int    g_deg[MAX_N];
__device__ int    g_off[MAX_N + 1];
__device__ int    g_cur[MAX_N];
__device__ int    g_csr[MAX_E];                 // src indices grouped by dst
__device__ __align__(256) __half g_xh[(size_t)MAX_N * D_IN];   // fp16 x copy

// Per-block inline dtype detect: for int64 (little-endian) edge indices, all
// odd 32-bit words of the first 256 entries are zero. Returns 1 if int64.
__device__ __forceinline__ int detect_i64(const unsigned int* w, unsigned* s_or) {
    if (threadIdx.x == 0) *s_or = 0u;
    __syncthreads();
    if (threadIdx.x < 128) {
        unsigned v = w[2 * threadIdx.x + 1] | w[2 * threadIdx.x + 257];
        if (v) atomicOr(s_or, 1u);
    }
    __syncthreads();
    return (*s_or == 0u) ? 1 : 0;
}

// ---------------- K0: degree histogram + x -> fp16 conversion --------------
__global__ void k_count(const float* __restrict__ x, const void* __restrict__ ei,
                        int E, int n8) {
    __shared__ unsigned s_or;
    int is64 = detect_i64((const unsigned int*)ei, &s_or);
    int e = blockIdx.x * blockDim.x + threadIdx.x;

    if (e < n8) {   // convert 8 floats -> 8 halves (16 B out)
        const float4* xv4 = (const float4*)x;
        float4 a = xv4[(size_t)e * 2];
        float4 b = xv4[(size_t)e * 2 + 1];
        __half2 h0 = __float22half2_rn(make_float2(a.x, a.y));
        __half2 h1 = __float22half2_rn(make_float2(a.z, a.w));
        __half2 h2 = __float22half2_rn(make_float2(b.x, b.y));
        __half2 h3 = __float22half2_rn(make_float2(b.z, b.w));
        uint4 o;
        o.x = reinterpret_cast<uint32_t&>(h0);
        o.y = reinterpret_cast<uint32_t&>(h1);
        o.z = reinterpret_cast<uint32_t&>(h2);
        o.w = reinterpret_cast<uint32_t&>(h3);
        ((uint4*)g_xh)[e] = o;
    }

    if (e >= E) return;
    int d;
    if (is64) d = (int)((const long long*)ei)[(size_t)E + e];
    else      d = ((const int*)ei)[E + e];
    atomicAdd(&g_deg[d], 1);
}

// ---------------- K1: merged exclusive scan (redundant global prefix) ------
__global__ __launch_bounds__(1024) void k_scan(int n, int E) {
    __shared__ int red[32];
    __shared__ int wpre[32];
    int t = threadIdx.x;
    int lane = t & 31;
    int wid = t >> 5;
    int chunk0 = blockIdx.x << 10;

    int pre = 0;
    for (int i = t; i < chunk0; i += 1024) pre += g_deg[i];
#pragma unroll
    for (int o = 16; o >= 1; o >>= 1) pre += __shfl_xor_sync(0xffffffffu, pre, o);
    if (lane == 0) red[wid] = pre;
    __syncthreads();
    if (t < 32) {
        int v = red[t];
#pragma unroll
        for (int o = 16; o >= 1; o >>= 1) v += __shfl_xor_sync(0xffffffffu, v, o);
        if (t == 0) red[0] = v;
    }
    __syncthreads();
    int prefix = red[0];

    int i = chunk0 + t;
    int d = (i < n) ? g_deg[i] : 0;
    int inc = d;
#pragma unroll
    for (int o = 1; o < 32; o <<= 1) {
        int v = __shfl_up_sync(0xffffffffu, inc, o);
        if (lane >= o) inc += v;
    }
    if (lane == 31) wpre[wid] = inc;
    __syncthreads();
    if (wid == 0) {
        int s = wpre[lane];
        int si = s;
#pragma unroll
        for (int o = 1; o < 32; o <<= 1) {
            int v = __shfl_up_sync(0xffffffffu, si, o);
            if (lane >= o) si += v;
        }
        wpre[lane] = si - s;
    }
    __syncthreads();
    if (i < n) {
        int off = prefix + inc - d + wpre[wid];
        g_off[i] = off;
        g_cur[i] = off;
    }
    if (blockIdx.x == gridDim.x - 1 && t == 0) g_off[n] = E;
}

// ---------------- K2: scatter src into CSR buckets + re-zero g_deg ---------
__global__ void k_scatter(const void* __restrict__ ei, int E, int n) {
    __shared__ unsigned s_or;
    int is64 = detect_i64((const unsigned int*)ei, &s_or);
    int e = blockIdx.x * blockDim.x + threadIdx.x;
    if (e < n) g_deg[e] = 0;
    if (e >= E) return;
    int s, d;
    if (is64) {
        const long long* p = (const long long*)ei;
        s = (int)p[e];
        d = (int)p[(size_t)E + e];
    } else {
        const int* p = (const int*)ei;
        s = p[e];
        d = p[E + e];
    }
    int pos = atomicAdd(&g_cur[d], 1);
    g_csr[pos] = s;
}

// ---------------- helpers ---------------------------------------------------
__device__ __forceinline__ void mma_f16(float* d,
                                        uint32_t a0, uint32_t a1,
                                        uint32_t a2, uint32_t a3,
                                        uint32_t b0, uint32_t b1) {
    asm volatile(
        "mma.sync.aligned.m16n8k16.row.col.f32.f16.f16.f32 "
        "{%0,%1,%2,%3}, {%4,%5,%6,%7}, {%8,%9}, {%0,%1,%2,%3};"
        : "+f"(d[0]), "+f"(d[1]), "+f"(d[2]), "+f"(d[3])
        : "r"(a0), "r"(a1), "r"(a2), "r"(a3), "r"(b0), "r"(b1));
}

__device__ __forceinline__ __half2 hmax2u(__half2 a, uint32_t ub) {
    return __hmax2(a, *(__half2*)&ub);
}

// ---------------- K3: fused streamed gather-max + fp16 MMA + log_softmax ---
// Per block: 64 nodes, 256 threads (8 warps).
//   G: warp w streams the CONTIGUOUS CSR edge range of its 8 nodes through a
//      rotating 8-deep register pipeline (one LDG.64/edge; idx prefetched one
//      iteration ahead). Pipeline slots are indexed by RELATIVE position
//      (g - e0) & 7 so the prologue's buf[j] (edge e0+j) lines up with the
//      consumption order (the R14 bug was absolute g & 7 indexing).
//      Node-boundary flushes are warp-uniform; no per-node pipeline drains.
//   L: stage Wl->Bsh (fp16), acc += agg @ Wl^T via m16n8k16
//   X: stage x(fp16)->Ash + Wr->Bsh, acc += x @ Wr^T
// Even blocks run G,L,X; odd blocks X,G,L (chip-level gather/MMA overlap).
__global__ __launch_bounds__(256) void k_aggemm(const float* __restrict__ Wl,
                                                const float* __restrict__ bl,
                                                const float* __restrict__ Wr,
                                                float* __restrict__ out, int N) {
    __shared__ uint32_t Ash[64][ROW_W];   // half2 words, k-order
    __shared__ uint32_t Bsh[64][ROW_W];   // col-major weights, half2 words

    int t = threadIdx.x;
    int w = t >> 5;
    int lane = t & 31;
    int nb = blockIdx.x * 64;

    int qid = lane >> 2;     // 0..7
    int tig = lane & 3;      // 0..3
    int wr = (w >> 1) * 16;  // warp node base
    int wn = (w & 1) * 32;   // warp output base

    float acc[4][4];
#pragma unroll
    for (int i = 0; i < 4; i++)
#pragma unroll
        for (int j = 0; j < 4; j++) acc[i][j] = 0.f;

    // ---- phase G: streamed register-pipelined fp16 gather-max into Ash ----
    auto phaseG = [&]() {
        const uint2* xh = (const uint2*)g_xh;    // 4 halves/lane, row stride 32
        const __half2 NINF2 = __half2half2(__ushort_as_half(0xFC00));
        const __half2 ZERO2 = __half2half2(__ushort_as_half(0));
        int n0 = nb + w * 8;
        auto offAt = [&](int i) { return g_off[min(n0 + i, N)]; };

        int e0 = offAt(0);
        int eEnd = offAt(8);
        uint2 buf[8];
        int idxNext = 0;
        if (eEnd > e0) {
#pragma unroll
            for (int j = 0; j < 8; j++) {
                int e = min(e0 + j, eEnd - 1);
                buf[j] = xh[(size_t)g_csr[e] * 32 + lane];
            }
            idxNext = g_csr[min(e0 + 8, eEnd - 1)];
        }

        __half2 a0 = NINF2, a1 = NINF2;
        bool has = false;
        int ln = 0;
        int nodeEnd = offAt(1);
        int g = e0;
        int slot = 0;                    // relative position (g - e0) & 7
#pragma unroll 1
        while (ln < 8) {
            if (g == nodeEnd) {          // flush node ln (zeros if no edges)
                __half2 o0 = has ? a0 : ZERO2;
                __half2 o1 = has ? a1 : ZERO2;
                uint2 st;
                st.x = reinterpret_cast<uint32_t&>(o0);
                st.y = reinterpret_cast<uint32_t&>(o1);
                *(uint2*)&Ash[w * 8 + ln][lane * 2] = st;
                a0 = NINF2; a1 = NINF2; has = false;
                ln++;
                if (ln < 8) nodeEnd = offAt(ln + 1);
                continue;
            }
            // consume edge g; refill its slot with edge g+8 (idx preloaded)
            uint2 v = buf[slot];
            buf[slot] = xh[(size_t)idxNext * 32 + lane];
            idxNext = g_csr[min(g + 9, eEnd - 1)];
            a0 = hmax2u(a0, v.x);
            a1 = hmax2u(a1, v.y);
            has = true;
            g++;
            slot = (slot + 1) & 7;
        }
        __syncthreads();
    };

    // ---- stage a weight matrix (fp32 [64][128]) -> Bsh fp16 col-major ----
    auto stageW = [&](const float* __restrict__ W) {
        int c = t >> 2;
        int q = t & 3;
        const float4* Wv = (const float4*)(W + (size_t)c * D_IN + q * 32);
#pragma unroll
        for (int j = 0; j < 4; j++) {
            float4 a = Wv[j * 2];
            float4 b = Wv[j * 2 + 1];
            __half2 h0 = __float22half2_rn(make_float2(a.x, a.y));
            __half2 h1 = __float22half2_rn(make_float2(a.z, a.w));
            __half2 h2 = __float22half2_rn(make_float2(b.x, b.y));
            __half2 h3 = __float22half2_rn(make_float2(b.z, b.w));
            uint4 o;
            o.x = reinterpret_cast<uint32_t&>(h0);
            o.y = reinterpret_cast<uint32_t&>(h1);
            o.z = reinterpret_cast<uint32_t&>(h2);
            o.w = reinterpret_cast<uint32_t&>(h3);
            *(uint4*)&Bsh[c][q * 16 + j * 4] = o;
        }
    };

    // ---- stage x (fp16 from g_xh) -> Ash ----
    auto stageX = [&]() {
        int ln = t >> 2;
        int q = t & 3;
        int n = nb + ln;
        const uint4* src = (const uint4*)(g_xh + (size_t)n * D_IN);
#pragma unroll
        for (int j = 0; j < 4; j++) {
            uint4 v = (n < N) ? src[q * 4 + j] : make_uint4(0, 0, 0, 0);
            *(uint4*)&Ash[ln][q * 16 + j * 4] = v;
        }
    };

    // ---- one full K=128 MMA pass over Ash x Bsh (8 k-steps, 4 n-tiles) ----
    auto mmaAll = [&]() {
#pragma unroll
        for (int ks = 0; ks < 8; ks++) {
            uint32_t a0 = Ash[wr + qid][ks * 8 + tig];
            uint32_t a1 = Ash[wr + qid + 8][ks * 8 + tig];
            uint32_t a2 = Ash[wr + qid][ks * 8 + tig + 4];
            uint32_t a3 = Ash[wr + qid + 8][ks * 8 + tig + 4];
#pragma unroll
            for (int tile = 0; tile < 4; tile++) {
                int col = wn + tile * 8 + qid;
                uint32_t b0 = Bsh[col][ks * 8 + tig];
                uint32_t b1 = Bsh[col][ks * 8 + tig + 4];
                mma_f16(acc[tile], a0, a1, a2, a3, b0, b1);
            }
        }
    };

    auto phaseL = [&]() { stageW(Wl); __syncthreads(); mmaAll(); __syncthreads(); };
    auto phaseX = [&]() { stageX(); stageW(Wr); __syncthreads(); mmaAll(); __syncthreads(); };

    if (blockIdx.x & 1) {
        phaseX();          // MMA first ...
        phaseG();          // ... while even blocks gather
        phaseL();
    } else {
        phaseG();
        phaseL();
        phaseX();
    }

    // ---- epilogue: acc fragments -> smem (+bias), then log_softmax --------
    float (*Os)[OS_PAD] = (float(*)[OS_PAD])Ash;   // overlay (mma consumed)
#pragma unroll
    for (int tile = 0; tile < 4; tile++) {
        int c = wn + tile * 8 + 2 * tig;
        int r0 = wr + qid;
        float b0 = bl[c], b1 = bl[c + 1];
        Os[r0][c]         = acc[tile][0] + b0;
        Os[r0][c + 1]     = acc[tile][1] + b1;
        Os[r0 + 8][c]     = acc[tile][2] + b0;
        Os[r0 + 8][c + 1] = acc[tile][3] + b1;
    }
    __syncthreads();

    // softmax: 4 threads per node row, 16 cols each
    {
        int row = t >> 2;
        int l4 = t & 3;
        float4 v[4];
#pragma unroll
        for (int j = 0; j < 4; j++)
            v[j] = *(const float4*)&Os[row][l4 * 16 + j * 4];

        float m = -CUDART_INF_F;
#pragma unroll
        for (int j = 0; j < 4; j++)
            m = fmaxf(m, fmaxf(fmaxf(v[j].x, v[j].y), fmaxf(v[j].z, v[j].w)));
        m = fmaxf(m, __shfl_xor_sync(0xffffffffu, m, 1));
        m = fmaxf(m, __shfl_xor_sync(0xffffffffu, m, 2));

        float s = 0.f;
#pragma unroll
        for (int j = 0; j < 4; j++)
            s += expf(v[j].x - m) + expf(v[j].y - m) +
                 expf(v[j].z - m) + expf(v[j].w - m);
        s += __shfl_xor_sync(0xffffffffu, s, 1);
        s += __shfl_xor_sync(0xffffffffu, s, 2);
        float lse = m + logf(s);

        int n = nb + row;
        if (n < N) {
#pragma unroll
            for (int j = 0; j < 4; j++) {
                float4 o4 = make_float4(v[j].x - lse, v[j].y - lse,
                                        v[j].z - lse, v[j].w - lse);
                *(float4*)(out + (size_t)n * D_OUT + l4 * 16 + j * 4) = o4;
            }
        }
    }
}

// ---------------- launcher -------------------------------------------------
extern "C" void kernel_launch(void* const* d_in, const int* in_sizes, int n_in,
                              void* d_out, int out_size) {
    const float* x  = (const float*)d_in[0];
    const void*  ei = d_in[1];
    const float* Wl = (const float*)d_in[2];
    const float* bl = (const float*)d_in[3];
    const float* Wr = (const float*)d_in[4];
    float* out = (float*)d_out;

    int N = in_sizes[0] / D_IN;
    int E = in_sizes[1] / 2;
    int n8 = N * (D_IN / 8);            // conversion threads (8 halves each)
    int g0 = (max(E, n8) + 255) / 256;

    // Launch order: ncu profiles OUR index 3 => k_aggemm.
    k_count<<<g0, 256>>>(x, ei, E, n8);                             // 0
    k_scan<<<(N + 1023) / 1024, 1024>>>(N, E);                      // 1
    k_scatter<<<(E + 255) / 256, 256>>>(ei, E, N);                  // 2
    k_aggemm<<<(N + 63) / 64, 256>>>(Wl, bl, Wr, out, N);           // 3
}

// round 16
// speedup vs baseline: 1.5659x; 1.5659x over previous
#include <cuda_runtime.h>
#include <cuda_fp16.h>
#include <math_constants.h>
#include <stdint.h>

// Problem constants (shapes fixed by the reference).
#define MAX_N 100032
#define MAX_E 1600000
#define D_IN  128
#define D_OUT 64

#define ROW_W 68     // half2-words per smem row (64 data + 4 pad); 272 B, 16B-aligned
#define OS_PAD 68    // epilogue float pitch (overlays Ash exactly)

// ---------------- Scratch (static __device__ globals; no runtime allocs) ---
// g_deg is zero at module load; k_scatter re-zeroes it for the NEXT invocation
// (graph replays run the identical sequence, so the invariant holds).
__device__ int    g_deg[MAX_N];
__device__ int    g_off[MAX_N + 1];
__device__ int    g_cur[MAX_N];
__device__ int    g_csr[MAX_E];                 // src indices grouped by dst
__device__ __align__(256) __half g_xh[(size_t)MAX_N * D_IN];    // fp16 x
__device__ __align__(256) __half g_aggh[(size_t)MAX_N * D_IN];  // fp16 agg

// Per-block inline dtype detect: for int64 (little-endian) edge indices, all
// odd 32-bit words of the first 256 entries are zero. Returns 1 if int64.
__device__ __forceinline__ int detect_i64(const unsigned int* w, unsigned* s_or) {
    if (threadIdx.x == 0) *s_or = 0u;
    __syncthreads();
    if (threadIdx.x < 128) {
        unsigned v = w[2 * threadIdx.x + 1] | w[2 * threadIdx.x + 257];
        if (v) atomicOr(s_or, 1u);
    }
    __syncthreads();
    return (*s_or == 0u) ? 1 : 0;
}

// ---------------- K0: degree histogram + x -> fp16 conversion --------------
__global__ void k_count(const float* __restrict__ x, const void* __restrict__ ei,
                        int E, int n8) {
    __shared__ unsigned s_or;
    int is64 = detect_i64((const unsigned int*)ei, &s_or);
    int e = blockIdx.x * blockDim.x + threadIdx.x;

    if (e < n8) {   // convert 8 floats -> 8 halves (16 B out)
        const float4* xv4 = (const float4*)x;
        float4 a = xv4[(size_t)e * 2];
        float4 b = xv4[(size_t)e * 2 + 1];
        __half2 h0 = __float22half2_rn(make_float2(a.x, a.y));
        __half2 h1 = __float22half2_rn(make_float2(a.z, a.w));
        __half2 h2 = __float22half2_rn(make_float2(b.x, b.y));
        __half2 h3 = __float22half2_rn(make_float2(b.z, b.w));
        uint4 o;
        o.x = reinterpret_cast<uint32_t&>(h0);
        o.y = reinterpret_cast<uint32_t&>(h1);
        o.z = reinterpret_cast<uint32_t&>(h2);
        o.w = reinterpret_cast<uint32_t&>(h3);
        ((uint4*)g_xh)[e] = o;
    }

    if (e >= E) return;
    int d;
    if (is64) d = (int)((const long long*)ei)[(size_t)E + e];
    else      d = ((const int*)ei)[E + e];
    atomicAdd(&g_deg[d], 1);
}

// ---------------- K1: merged exclusive scan (redundant global prefix) ------
__global__ __launch_bounds__(1024) void k_scan(int n, int E) {
    __shared__ int red[32];
    __shared__ int wpre[32];
    int t = threadIdx.x;
    int lane = t & 31;
    int wid = t >> 5;
    int chunk0 = blockIdx.x << 10;

    int pre = 0;
    for (int i = t; i < chunk0; i += 1024) pre += g_deg[i];
#pragma unroll
    for (int o = 16; o >= 1; o >>= 1) pre += __shfl_xor_sync(0xffffffffu, pre, o);
    if (lane == 0) red[wid] = pre;
    __syncthreads();
    if (t < 32) {
        int v = red[t];
#pragma unroll
        for (int o = 16; o >= 1; o >>= 1) v += __shfl_xor_sync(0xffffffffu, v, o);
        if (t == 0) red[0] = v;
    }
    __syncthreads();
    int prefix = red[0];

    int i = chunk0 + t;
    int d = (i < n) ? g_deg[i] : 0;
    int inc = d;
#pragma unroll
    for (int o = 1; o < 32; o <<= 1) {
        int v = __shfl_up_sync(0xffffffffu, inc, o);
        if (lane >= o) inc += v;
    }
    if (lane == 31) wpre[wid] = inc;
    __syncthreads();
    if (wid == 0) {
        int s = wpre[lane];
        int si = s;
#pragma unroll
        for (int o = 1; o < 32; o <<= 1) {
            int v = __shfl_up_sync(0xffffffffu, si, o);
            if (lane >= o) si += v;
        }
        wpre[lane] = si - s;
    }
    __syncthreads();
    if (i < n) {
        int off = prefix + inc - d + wpre[wid];
        g_off[i] = off;
        g_cur[i] = off;
    }
    if (blockIdx.x == gridDim.x - 1 && t == 0) g_off[n] = E;
}

// ---------------- K2: scatter src into CSR buckets + re-zero g_deg ---------
__global__ void k_scatter(const void* __restrict__ ei, int E, int n) {
    __shared__ unsigned s_or;
    int is64 = detect_i64((const unsigned int*)ei, &s_or);
    int e = blockIdx.x * blockDim.x + threadIdx.x;
    if (e < n) g_deg[e] = 0;
    if (e >= E) return;
    int s, d;
    if (is64) {
        const long long* p = (const long long*)ei;
        s = (int)p[e];
        d = (int)p[(size_t)E + e];
    } else {
        const int* p = (const int*)ei;
        s = p[e];
        d = p[E + e];
    }
    int pos = atomicAdd(&g_cur[d], 1);
    g_csr[pos] = s;
}

// ---------------- helpers ---------------------------------------------------
__device__ __forceinline__ void mma_f16(float* d,
                                        uint32_t a0, uint32_t a1,
                                        uint32_t a2, uint32_t a3,
                                        uint32_t b0, uint32_t b1) {
    asm volatile(
        "mma.sync.aligned.m16n8k16.row.col.f32.f16.f16.f32 "
        "{%0,%1,%2,%3}, {%4,%5,%6,%7}, {%8,%9}, {%0,%1,%2,%3};"
        : "+f"(d[0]), "+f"(d[1]), "+f"(d[2]), "+f"(d[3])
        : "r"(a0), "r"(a1), "r"(a2), "r"(a3), "r"(b0), "r"(b1));
}

__device__ __forceinline__ __half2 hmax2u(__half2 a, uint32_t ub) {
    return __hmax2(a, *(__half2*)&ub);
}

// ---------------- K3: standalone warp-per-node fp16 gather-max -------------
// One warp per node; lane covers 4 halves (uint2 = 8 B). 4-edge batches keep
// 4 independent loads in flight; whole chip's warps gather concurrently.
__global__ __launch_bounds__(256) void k_gather(int N) {
    int gt = blockIdx.x * blockDim.x + threadIdx.x;
    int node = gt >> 5;
    int lane = gt & 31;
    if (node >= N) return;

    const uint2* xh = (const uint2*)g_xh;
    const __half2 NINF2 = __half2half2(__ushort_as_half(0xFC00));
    __half2 m0 = __half2half2(__ushort_as_half(0));
    __half2 m1 = m0;

    int beg = g_off[node];
    int end = g_off[node + 1];
    if (beg < end) {
        m0 = NINF2; m1 = NINF2;
        int e = beg;
        for (; e + 3 < end; e += 4) {
            int s0 = g_csr[e];
            int s1 = g_csr[e + 1];
            int s2 = g_csr[e + 2];
            int s3 = g_csr[e + 3];
            uint2 v0 = xh[(size_t)s0 * 32 + lane];
            uint2 v1 = xh[(size_t)s1 * 32 + lane];
            uint2 v2 = xh[(size_t)s2 * 32 + lane];
            uint2 v3 = xh[(size_t)s3 * 32 + lane];
            m0 = __hmax2(__hmax2(hmax2u(m0, v0.x), *(__half2*)&v1.x),
                         __hmax2(*(__half2*)&v2.x, *(__half2*)&v3.x));
            m1 = __hmax2(__hmax2(hmax2u(m1, v0.y), *(__half2*)&v1.y),
                         __hmax2(*(__half2*)&v2.y, *(__half2*)&v3.y));
        }
        for (; e < end; e++) {
            int s0 = g_csr[e];
            uint2 v0 = xh[(size_t)s0 * 32 + lane];
            m0 = hmax2u(m0, v0.x);
            m1 = hmax2u(m1, v0.y);
        }
    }
    uint2 st;
    st.x = reinterpret_cast<uint32_t&>(m0);
    st.y = reinterpret_cast<uint32_t&>(m1);
    ((uint2*)g_aggh)[(size_t)node * 32 + lane] = st;
}

// ---------------- K4: fp16 MMA GEMM + bias + log_softmax -------------------
// Per block: 64 nodes, 256 threads. Two passes over K=128:
//   pass 1: A = g_aggh, W = Wl;  pass 2: A = g_xh, W = Wr.
__global__ __launch_bounds__(256) void k_gemm(const float* __restrict__ Wl,
                                              const float* __restrict__ bl,
                                              const float* __restrict__ Wr,
                                              float* __restrict__ out, int N) {
    __shared__ uint32_t Ash[64][ROW_W];   // half2 words, k-order
    __shared__ uint32_t Bsh[64][ROW_W];   // col-major weights, half2 words

    int t = threadIdx.x;
    int w = t >> 5;
    int lane = t & 31;
    int nb = blockIdx.x * 64;

    int qid = lane >> 2;     // 0..7
    int tig = lane & 3;      // 0..3
    int wr = (w >> 1) * 16;  // warp node base
    int wn = (w & 1) * 32;   // warp output base

    float acc[4][4];
#pragma unroll
    for (int i = 0; i < 4; i++)
#pragma unroll
        for (int j = 0; j < 4; j++) acc[i][j] = 0.f;

    // stage an fp16 A matrix (g_aggh or g_xh rows nb..nb+63) -> Ash
    auto stageA = [&](const __half* __restrict__ src) {
        int ln = t >> 2;
        int q = t & 3;
        int n = nb + ln;
        const uint4* s4 = (const uint4*)(src + (size_t)n * D_IN);
#pragma unroll
        for (int j = 0; j < 4; j++) {
            uint4 v = (n < N) ? s4[q * 4 + j] : make_uint4(0, 0, 0, 0);
            *(uint4*)&Ash[ln][q * 16 + j * 4] = v;
        }
    };

    // stage a weight matrix (fp32 [64][128]) -> Bsh fp16 col-major
    auto stageW = [&](const float* __restrict__ W) {
        int c = t >> 2;
        int q = t & 3;
        const float4* Wv = (const float4*)(W + (size_t)c * D_IN + q * 32);
#pragma unroll
        for (int j = 0; j < 4; j++) {
            float4 a = Wv[j * 2];
            float4 b = Wv[j * 2 + 1];
            __half2 h0 = __float22half2_rn(make_float2(a.x, a.y));
            __half2 h1 = __float22half2_rn(make_float2(a.z, a.w));
            __half2 h2 = __float22half2_rn(make_float2(b.x, b.y));
            __half2 h3 = __float22half2_rn(make_float2(b.z, b.w));
            uint4 o;
            o.x = reinterpret_cast<uint32_t&>(h0);
            o.y = reinterpret_cast<uint32_t&>(h1);
            o.z = reinterpret_cast<uint32_t&>(h2);
            o.w = reinterpret_cast<uint32_t&>(h3);
            *(uint4*)&Bsh[c][q * 16 + j * 4] = o;
        }
    };

    // one full K=128 MMA pass over Ash x Bsh (8 k-steps, 4 n-tiles)
    auto mmaAll = [&]() {
#pragma unroll
        for (int ks = 0; ks < 8; ks++) {
            uint32_t a0 = Ash[wr + qid][ks * 8 + tig];
            uint32_t a1 = Ash[wr + qid + 8][ks * 8 + tig];
            uint32_t a2 = Ash[wr + qid][ks * 8 + tig + 4];
            uint32_t a3 = Ash[wr + qid + 8][ks * 8 + tig + 4];
#pragma unroll
            for (int tile = 0; tile < 4; tile++) {
                int col = wn + tile * 8 + qid;
                uint32_t b0 = Bsh[col][ks * 8 + tig];
                uint32_t b1 = Bsh[col][ks * 8 + tig + 4];
                mma_f16(acc[tile], a0, a1, a2, a3, b0, b1);
            }
        }
    };

    stageA(g_aggh); stageW(Wl); __syncthreads(); mmaAll(); __syncthreads();
    stageA(g_xh);   stageW(Wr); __syncthreads(); mmaAll(); __syncthreads();

    // ---- epilogue: acc fragments -> smem (+bias), then log_softmax --------
    float (*Os)[OS_PAD] = (float(*)[OS_PAD])Ash;   // overlay (mma consumed)
#pragma unroll
    for (int tile = 0; tile < 4; tile++) {
        int c = wn + tile * 8 + 2 * tig;
        int r0 = wr + qid;
        float b0 = bl[c], b1 = bl[c + 1];
        Os[r0][c]         = acc[tile][0] + b0;
        Os[r0][c + 1]     = acc[tile][1] + b1;
        Os[r0 + 8][c]     = acc[tile][2] + b0;
        Os[r0 + 8][c + 1] = acc[tile][3] + b1;
    }
    __syncthreads();

    // softmax: 4 threads per node row, 16 cols each
    {
        int row = t >> 2;
        int l4 = t & 3;
        float4 v[4];
#pragma unroll
        for (int j = 0; j < 4; j++)
            v[j] = *(const float4*)&Os[row][l4 * 16 + j * 4];

        float m = -CUDART_INF_F;
#pragma unroll
        for (int j = 0; j < 4; j++)
            m = fmaxf(m, fmaxf(fmaxf(v[j].x, v[j].y), fmaxf(v[j].z, v[j].w)));
        m = fmaxf(m, __shfl_xor_sync(0xffffffffu, m, 1));
        m = fmaxf(m, __shfl_xor_sync(0xffffffffu, m, 2));

        float s = 0.f;
#pragma unroll
        for (int j = 0; j < 4; j++)
            s += expf(v[j].x - m) + expf(v[j].y - m) +
                 expf(v[j].z - m) + expf(v[j].w - m);
        s += __shfl_xor_sync(0xffffffffu, s, 1);
        s += __shfl_xor_sync(0xffffffffu, s, 2);
        float lse = m + logf(s);

        int n = nb + row;
        if (n < N) {
#pragma unroll
            for (int j = 0; j < 4; j++) {
                float4 o4 = make_float4(v[j].x - lse, v[j].y - lse,
                                        v[j].z - lse, v[j].w - lse);
                *(float4*)(out + (size_t)n * D_OUT + l4 * 16 + j * 4) = o4;
            }
        }
    }
}

// ---------------- launcher -------------------------------------------------
extern "C" void kernel_launch(void* const* d_in, const int* in_sizes, int n_in,
                              void* d_out, int out_size) {
    const float* x  = (const float*)d_in[0];
    const void*  ei = d_in[1];
    const float* Wl = (const float*)d_in[2];
    const float* bl = (const float*)d_in[3];
    const float* Wr = (const float*)d_in[4];
    float* out = (float*)d_out;

    int N = in_sizes[0] / D_IN;
    int E = in_sizes[1] / 2;
    int n8 = N * (D_IN / 8);            // conversion threads (8 halves each)
    int g0 = (max(E, n8) + 255) / 256;

    // Launch order: ncu profiles OUR index 3 => k_gather.
    k_count<<<g0, 256>>>(x, ei, E, n8);                             // 0
    k_scan<<<(N + 1023) / 1024, 1024>>>(N, E);                      // 1
    k_scatter<<<(E + 255) / 256, 256>>>(ei, E, N);                  // 2
    k_gather<<<(N * 32 + 255) / 256, 256>>>(N);                     // 3
    k_gemm<<<(N + 63) / 64, 256>>>(Wl, bl, Wr, out, N);             // 4
}